// round 13
// baseline (speedup 1.0000x reference)
#include <cuda_runtime.h>
#include <cuda_bf16.h>
#include <math.h>
#include <stdint.h>

#define Bdim 4
#define Tdim 512
#define Hdim 32
#define Ndim 64
#define Ddim 2048           // Hdim*Ndim
#define Mtot (Bdim*Tdim)    // 2048
#define Ktot Ddim           // 2048

typedef unsigned long long ull;

// ---------------- device scratch (no allocs allowed) ----------------
__device__ float          g_d [Bdim * Tdim * Ddim];   // decay
__device__ float          g_kk[Bdim * Tdim * Ddim];   // kk, overwritten with qq_m = D_m.kk_m
__device__ float          g_bb[Bdim * Tdim * Ddim];   // kk * sigmoid(iclr)
__device__ float          g_sc[Bdim * Hdim * (Tdim/4) * 12];  // window scalars
__device__ __nv_bfloat16  g_Ahi[Mtot * Ktot];         // y hi (bf16)
__device__ __nv_bfloat16  g_Alo[Mtot * Ktot];         // y lo (bf16)
__device__ __nv_bfloat16  g_Wb [Ddim * Ktot];         // W (bf16, exact)

// ---------------- PTX helpers (plain sm_80+/sm_100 features only) --------
__device__ __forceinline__ uint32_t smem_u32(const void* p) {
    return (uint32_t)__cvta_generic_to_shared(p);
}
__device__ __forceinline__ void cp_async16(uint32_t smaddr, const void* g) {
    asm volatile("cp.async.cg.shared.global [%0], [%1], 16;" :: "r"(smaddr), "l"(g));
}
#define CP_COMMIT() asm volatile("cp.async.commit_group;" ::: "memory")
#define CP_WAIT(n)  asm volatile("cp.async.wait_group %0;" :: "n"(n) : "memory")

__device__ __forceinline__ void ldsm_x4(uint32_t* r, uint32_t addr) {
    asm volatile("ldmatrix.sync.aligned.m8n8.x4.shared.b16 {%0,%1,%2,%3}, [%4];"
        : "=r"(r[0]), "=r"(r[1]), "=r"(r[2]), "=r"(r[3]) : "r"(addr));
}
__device__ __forceinline__ void mma_bf16(float* d, const uint32_t* a, const uint32_t* b) {
    asm volatile("mma.sync.aligned.m16n8k16.row.col.f32.bf16.bf16.f32 "
        "{%0,%1,%2,%3}, {%4,%5,%6,%7}, {%8,%9}, {%0,%1,%2,%3};"
        : "+f"(d[0]), "+f"(d[1]), "+f"(d[2]), "+f"(d[3])
        : "r"(a[0]), "r"(a[1]), "r"(a[2]), "r"(a[3]), "r"(b[0]), "r"(b[1]));
}

// ---- packed f32x2 (sm_100+ plain PTX) ----
__device__ __forceinline__ ull pack2(float lo, float hi) {
    ull r; asm("mov.b64 %0, {%1, %2};" : "=l"(r) : "f"(lo), "f"(hi)); return r;
}
__device__ __forceinline__ void unpack2(ull v, float& lo, float& hi) {
    asm("mov.b64 {%0, %1}, %2;" : "=f"(lo), "=f"(hi) : "l"(v));
}
__device__ __forceinline__ ull fma2(ull a, ull b, ull c) {
    ull d; asm("fma.rn.f32x2 %0, %1, %2, %3;" : "=l"(d) : "l"(a), "l"(b), "l"(c));
    return d;
}
__device__ __forceinline__ ull mul2(ull a, ull b) {
    ull d; asm("mul.rn.f32x2 %0, %1, %2;" : "=l"(d) : "l"(a), "l"(b)); return d;
}
__device__ __forceinline__ ull add2(ull a, ull b) {
    ull d; asm("add.rn.f32x2 %0, %1, %2;" : "=l"(d) : "l"(a), "l"(b)); return d;
}

// ---------------------------------------------------------------------------
// Kernel 0a: elementwise precompute (decay, kk, b)
// ---------------------------------------------------------------------------
__global__ void __launch_bounds__(256) wkv7_pre_kernel(
    const float* __restrict__ w, const float* __restrict__ k,
    const float* __restrict__ iclr)
{
    const int vec  = blockIdx.x * 8 + (threadIdx.x >> 5);
    const int lane = threadIdx.x & 31;
    const size_t base = (size_t)vec * Ndim;

    float k0 = k[base + lane], k1 = k[base + lane + 32];
    float p = fmaf(k0, k0, k1 * k1);
#pragma unroll
    for (int o = 16; o; o >>= 1) p += __shfl_xor_sync(0xffffffffu, p, o);
    const float inv = rsqrtf(p + 1e-12f);

    float w0 = w[base + lane], w1 = w[base + lane + 32];
    float c0 = iclr[base + lane], c1 = iclr[base + lane + 32];

    g_d[base + lane]      = __expf(-__expf(w0));
    g_d[base + lane + 32] = __expf(-__expf(w1));
    const float kk0 = k0 * inv, kk1 = k1 * inv;
    g_kk[base + lane]      = kk0;
    g_kk[base + lane + 32] = kk1;
    g_bb[base + lane]      = kk0 / (1.0f + __expf(-c0));
    g_bb[base + lane + 32] = kk1 / (1.0f + __expf(-c1));
}

// ---------------------------------------------------------------------------
// Kernel 0b: Wq (int32) -> bf16 (exact, |v|<=128)
// ---------------------------------------------------------------------------
__global__ void __launch_bounds__(256) wconv_kernel(const int* __restrict__ wq)
{
    const size_t i4 = (size_t)blockIdx.x * 256 + threadIdx.x;   // int4 index
    int4 q = ((const int4*)wq)[i4];
    __nv_bfloat16 o[4];
    o[0] = __float2bfloat16((float)q.x);
    o[1] = __float2bfloat16((float)q.y);
    o[2] = __float2bfloat16((float)q.z);
    o[3] = __float2bfloat16((float)q.w);
    *(uint2*)&g_Wb[i4 * 4] = *(uint2*)o;
}

// ---------------------------------------------------------------------------
// Kernel 0c: per-window (4 steps) lookahead precompute. One warp per window.
// Writes qq_m = D_m (.) kk_m over g_kk (m=1..3; qq_0 = kk_0 unchanged), and
// 12 scalars [a01,a02,a03,a12,a13,a23,b01,b02,b03,b12,b13,b23] to g_sc.
// ---------------------------------------------------------------------------
__global__ void __launch_bounds__(256) wkv7_win_kernel(const float* __restrict__ k)
{
    const int win  = blockIdx.x * 8 + (threadIdx.x >> 5);   // 0..16383
    const int lane = threadIdx.x & 31;
    const int ss = win & 127;
    const int h  = (win >> 7) & 31;
    const int b  = win >> 12;
    const int t  = ss * 4;
    const size_t base  = (((size_t)b * Tdim + t) * Hdim + h) * Ndim;
    const size_t tstep = (size_t)Hdim * Ndim;

    float p[12];
#pragma unroll
    for (int i = 0; i < 12; i++) p[i] = 0.f;

    float qq1c[2], qq2c[2], qq3c[2];
#pragma unroll
    for (int c = 0; c < 2; c++) {
        const int j = lane + c * 32;
        const float d0 = g_d[base + j];
        const float d1 = g_d[base + tstep + j];
        const float d2 = g_d[base + 2 * tstep + j];
        const float kk1 = g_kk[base + tstep + j];
        const float kk2 = g_kk[base + 2 * tstep + j];
        const float kk3 = g_kk[base + 3 * tstep + j];
        const float b0 = g_bb[base + j];
        const float b1 = g_bb[base + tstep + j];
        const float b2 = g_bb[base + 2 * tstep + j];
        const float k0 = k[base + j];
        const float k1v = k[base + tstep + j];
        const float k2v = k[base + 2 * tstep + j];

        const float D1 = d0, D2 = d0 * d1, D3 = D2 * d2;
        qq1c[c] = D1 * kk1; qq2c[c] = D2 * kk2; qq3c[c] = D3 * kk3;

        const float e12 = d1, e13 = d1 * d2, e23 = d2;
        p[0]  += b0 * kk1;
        p[1]  += b0 * e12 * kk2;
        p[2]  += b0 * e13 * kk3;
        p[3]  += b1 * kk2;
        p[4]  += b1 * e23 * kk3;
        p[5]  += b2 * kk3;
        p[6]  += k0 * kk1;
        p[7]  += k0 * e12 * kk2;
        p[8]  += k0 * e13 * kk3;
        p[9]  += k1v * kk2;
        p[10] += k1v * e23 * kk3;
        p[11] += k2v * kk3;
    }
#pragma unroll
    for (int c = 0; c < 2; c++) {
        const int j = lane + c * 32;
        g_kk[base + tstep + j]     = qq1c[c];
        g_kk[base + 2 * tstep + j] = qq2c[c];
        g_kk[base + 3 * tstep + j] = qq3c[c];
    }
#pragma unroll
    for (int m = 16; m; m >>= 1)
#pragma unroll
        for (int i = 0; i < 12; i++) p[i] += __shfl_xor_sync(0xffffffffu, p[i], m);

    if (lane == 0) {
        float4* dst = (float4*)&g_sc[(size_t)win * 12];
        dst[0] = make_float4(p[0], p[1], p[2],  p[3]);
        dst[1] = make_float4(p[4], p[5], p[6],  p[7]);
        dst[2] = make_float4(p[8], p[9], p[10], p[11]);
    }
}

// ---------------------------------------------------------------------------
// Kernel 1: WKV scan, 4-step lookahead form. One block (256 thr) per (b,h).
// seg = tid&15 (4 cols), rp = tid>>4 (4 rows). Per window: 4 dots against the
// base state, ONE merged allreduce, in-lane recurrence, shfl.idx allgather,
// 4 pure-FMA state updates. y partials stay PACKED f32x2 (STS.64) and are
// reduced (LDS.128 + add2) at the next window's barrier.
// ---------------------------------------------------------------------------
#define SLOT_F (6 * Ndim)               // 384 floats per step slot
#define YROW_F 34                       // packed y row stride (32 + 2 pad)
#define YBUF_F (2 * 4 * 64 * YROW_F)    // 17408 floats
#define SCAN_SMEM ((8 * SLOT_F + YBUF_F + 24) * 4)

__global__ void __launch_bounds__(256) wkv7_scan_kernel(
    const float* __restrict__ r, const float* __restrict__ k,
    const float* __restrict__ v)
{
    extern __shared__ __align__(16) float dsm[];
    float* sbuf  = dsm;                         // [8][384]
    float* ybuf  = dsm + 8 * SLOT_F;            // [2][4][64][34]
    float* scbuf = ybuf + YBUF_F;               // [2][12]

    const int bh = blockIdx.x;          // 0..127
    const int b  = bh >> 5;
    const int h  = bh & 31;
    const int tid = threadIdx.x;
    const int seg = tid & 15;           // 0..15 (4-col segment)
    const int rp  = tid >> 4;           // 0..15 (row quad)
    const int row0 = rp * 4;
    const int jb  = seg * 4;            // column base
    const int bs0 = seg & 1;
    const int bs1 = (seg >> 1) & 1;
    const int q   = seg & 3;            // owned local row after reduce-scatter
    const int lane = tid & 31;
    const int gsrc0 = lane & 16;        // allgather shfl.idx source base

    ull st[4][2];
    const ull zero2 = pack2(0.f, 0.f);
#pragma unroll
    for (int i = 0; i < 4; i++) { st[i][0] = zero2; st[i][1] = zero2; }

    // vector loaders: lanes 0..11 of each warp -> 96 loaders, 1 float4/step
    const int wl   = tid >> 5;
    const bool is_loader = (lane < 12);
    const int lidx = wl * 12 + lane;        // 0..95
    const int lvec = lidx >> 4;             // 0..5
    const int lq   = lidx & 15;             // 0..15
    const size_t vstep = (size_t)Hdim * Ndim / 4;   // float4 per t

    const float4* gbase = nullptr;
    uint32_t sdst = 0;
    if (is_loader) {
        const float* sp;
        switch (lvec) {
            case 0: sp = g_d;  break;
            case 1: sp = g_kk; break;   // qq
            case 2: sp = g_bb; break;
            case 3: sp = k;    break;
            case 4: sp = r;    break;
            default: sp = v;   break;
        }
        gbase = (const float4*)sp + (((size_t)b * Tdim) * Hdim + h) * (Ndim / 4) + lq;
        sdst  = smem_u32(sbuf) + lidx * 16;
    }
    const uint32_t slot_bytes = SLOT_F * 4;     // 1536

    // scalar loaders: warp 0 lanes 12..14
    const bool is_scl = (tid >= 12 && tid < 15);
    const int  sli    = tid - 12;
    const size_t scgb = (size_t)((b * 32 + h) * 128) * 12;
    const uint32_t scs_base = smem_u32(scbuf);

    // y-reduction mapping (all 256 threads)
    const int ru   = tid >> 6;          // step-in-window 0..3
    const int rrow = tid & 63;          // row
    const size_t ybh = ((size_t)b * Tdim) * Ddim + h * Ndim;

    // prologue: issue window 0 (slots 0..3 + scalars slot 0)
    if (is_loader) {
#pragma unroll
        for (int u = 0; u < 4; u++)
            cp_async16(sdst + u * slot_bytes, gbase + (size_t)u * vstep);
    }
    if (is_scl)
        cp_async16(scs_base + sli * 16, g_sc + scgb + sli * 4);
    CP_COMMIT();

    const int NSS = Tdim / 4;           // 128 windows
    for (int ss = 0; ss < NSS; ss++) {
        const int t0 = ss * 4;
        CP_WAIT(0);
        __syncthreads();

        // ---- reduce previous window's y partials (packed f32x2) ----
        if (ss > 0) {
            const ull* yb = (const ull*)(ybuf
                + (((ss - 1) & 1) * 4 + ru) * (64 * YROW_F) + rrow * YROW_F);
            ull acc0 = add2(yb[0], yb[1]);
            ull acc1 = add2(yb[2], yb[3]);
            ull acc2 = add2(yb[4], yb[5]);
            ull acc3 = add2(yb[6], yb[7]);
            ull acc4 = add2(yb[8], yb[9]);
            ull acc5 = add2(yb[10], yb[11]);
            ull acc6 = add2(yb[12], yb[13]);
            ull acc7 = add2(yb[14], yb[15]);
            acc0 = add2(acc0, acc1); acc2 = add2(acc2, acc3);
            acc4 = add2(acc4, acc5); acc6 = add2(acc6, acc7);
            acc0 = add2(acc0, acc2); acc4 = add2(acc4, acc6);
            acc0 = add2(acc0, acc4);
            float slo, shi; unpack2(acc0, slo, shi);
            const float s = slo + shi;
            const size_t yi = ybh + (size_t)(t0 - 4 + ru) * Ddim + rrow;
            __nv_bfloat16 hi = __float2bfloat16(s);
            g_Ahi[yi] = hi;
            g_Alo[yi] = __float2bfloat16(s - __bfloat162float(hi));
        }

        // issue window ss+1
        if (is_loader) {
#pragma unroll
            for (int u = 0; u < 4; u++) {
                const int st4 = t0 + 4 + u;
                if (st4 < Tdim)
                    cp_async16(sdst + (st4 & 7) * slot_bytes, gbase + (size_t)st4 * vstep);
            }
        }
        if (is_scl && (ss + 1 < NSS))
            cp_async16(scs_base + ((ss + 1) & 1) * 48 + sli * 16,
                       g_sc + scgb + (size_t)(ss + 1) * 12 + sli * 4);
        CP_COMMIT();

        // ---- window compute ----
        const float* sl[4];
#pragma unroll
        for (int m = 0; m < 4; m++) sl[m] = sbuf + (((ss & 1) * 4 + m) * SLOT_F);

        // scalars
        const float4* scp = (const float4*)(scbuf + (ss & 1) * 12);
        const float4 sA = scp[0], sB = scp[1], sC = scp[2];
        const float a01 = sA.x, a02 = sA.y, a03 = sA.z, a12 = sA.w;
        const float a13 = sB.x, a23 = sB.y, b01 = sB.z, b02 = sB.w;
        const float b03 = sC.x, b12 = sC.y, b13 = sC.z, b23 = sC.w;

        // 4 dots against base state
        float pd[4][4];
#pragma unroll
        for (int m = 0; m < 4; m++) {
            const ulonglong2 qm = *(const ulonglong2*)(sl[m] + 64 + jb);
#pragma unroll
            for (int i = 0; i < 4; i++) {
                ull pp = fma2(st[i][0], qm.x, mul2(st[i][1], qm.y));
                float plo, phi; unpack2(pp, plo, phi);
                pd[m][i] = plo + phi;
            }
        }

        // merged allreduce: reduce-scatter rows (xor2, xor1), then xor4, xor8
        float u0[4], u1[4], val[4];
#pragma unroll
        for (int m = 0; m < 4; m++) {
            float sendA = bs1 ? pd[m][0] : pd[m][2];
            float sendB = bs1 ? pd[m][1] : pd[m][3];
            float rA = __shfl_xor_sync(0xffffffffu, sendA, 2);
            float rB = __shfl_xor_sync(0xffffffffu, sendB, 2);
            u0[m] = (bs1 ? pd[m][2] : pd[m][0]) + rA;
            u1[m] = (bs1 ? pd[m][3] : pd[m][1]) + rB;
        }
#pragma unroll
        for (int m = 0; m < 4; m++) {
            float send = bs0 ? u0[m] : u1[m];
            float rr = __shfl_xor_sync(0xffffffffu, send, 1);
            val[m] = (bs0 ? u1[m] : u0[m]) + rr;
        }
#pragma unroll
        for (int m = 0; m < 4; m++) val[m] += __shfl_xor_sync(0xffffffffu, val[m], 4);
#pragma unroll
        for (int m = 0; m < 4; m++) val[m] += __shfl_xor_sync(0xffffffffu, val[m], 8);

        // in-lane recurrence for local row q
        const float v0q = sl[0][320 + row0 + q];
        const float v1q = sl[1][320 + row0 + q];
        const float v2q = sl[2][320 + row0 + q];
        float sar[4];
        sar[0] = -val[0];
        sar[1] = -(val[1] + sar[0] * a01 + v0q * b01);
        sar[2] = -(val[2] + sar[0] * a02 + sar[1] * a12 + v0q * b02 + v1q * b12);
        sar[3] = -(val[3] + sar[0] * a03 + sar[1] * a13 + sar[2] * a23
                   + v0q * b03 + v1q * b13 + v2q * b23);

        // allgather rows via shfl.idx: row-i total lives at lane (lane&16)|i
        float saX[4][4];
#pragma unroll
        for (int m = 0; m < 4; m++)
#pragma unroll
            for (int i = 0; i < 4; i++)
                saX[m][i] = __shfl_sync(0xffffffffu, sar[m], gsrc0 | i);

        // 4 state updates + packed deferred y partials
        float* ywb = ybuf + ((ss & 1) * 4) * (64 * YROW_F);
#pragma unroll
        for (int m = 0; m < 4; m++) {
            const float* s = sl[m];
            const ulonglong2 dv = *(const ulonglong2*)(s +   0 + jb);
            const ulonglong2 bv = *(const ulonglong2*)(s + 128 + jb);
            const ulonglong2 kv = *(const ulonglong2*)(s + 192 + jb);
            const ulonglong2 rv = *(const ulonglong2*)(s + 256 + jb);
            const float4 vv4 = *(const float4*)(s + 320 + row0);
            const float varr[4] = {vv4.x, vv4.y, vv4.z, vv4.w};
            float* yw = ywb + m * (64 * YROW_F);
#pragma unroll
            for (int i = 0; i < 4; i++) {
                const ull sa2 = pack2(saX[m][i], saX[m][i]);
                const ull v2  = pack2(varr[i], varr[i]);
                st[i][0] = fma2(st[i][0], dv.x, fma2(sa2, bv.x, mul2(v2, kv.x)));
                st[i][1] = fma2(st[i][1], dv.y, fma2(sa2, bv.y, mul2(v2, kv.y)));
                ull ya = fma2(st[i][0], rv.x, mul2(st[i][1], rv.y));
                *(ull*)(yw + (row0 + i) * YROW_F + seg * 2) = ya;
            }
        }
    }

    // tail: reduce the last window's y
    __syncthreads();
    {
        const ull* yb = (const ull*)(ybuf
            + (((NSS - 1) & 1) * 4 + ru) * (64 * YROW_F) + rrow * YROW_F);
        ull acc0 = add2(yb[0], yb[1]);
        ull acc1 = add2(yb[2], yb[3]);
        ull acc2 = add2(yb[4], yb[5]);
        ull acc3 = add2(yb[6], yb[7]);
        ull acc4 = add2(yb[8], yb[9]);
        ull acc5 = add2(yb[10], yb[11]);
        ull acc6 = add2(yb[12], yb[13]);
        ull acc7 = add2(yb[14], yb[15]);
        acc0 = add2(acc0, acc1); acc2 = add2(acc2, acc3);
        acc4 = add2(acc4, acc5); acc6 = add2(acc6, acc7);
        acc0 = add2(acc0, acc2); acc4 = add2(acc4, acc6);
        acc0 = add2(acc0, acc4);
        float slo, shi; unpack2(acc0, slo, shi);
        const float s = slo + shi;
        const size_t yi = ybh + (size_t)(Tdim - 4 + ru) * Ddim + rrow;
        __nv_bfloat16 hi = __float2bfloat16(s);
        g_Ahi[yi] = hi;
        g_Alo[yi] = __float2bfloat16(s - __bfloat162float(hi));
    }
}

// ---------------------------------------------------------------------------
// Kernel 2: mma.sync bf16 split GEMM (NT). 2-stage, 96KB (R10 exact, 87us).
// ---------------------------------------------------------------------------
#define NCH   (Ktot / 64)          // 32 K-chunks
#define STAGE 49152                // 3 tiles * 16KB
#define GSM_TOTAL (2 * STAGE)

__device__ __forceinline__ uint32_t swz(uint32_t row, uint32_t cbyte) {
    uint32_t off = row * 128 + cbyte;
    return off ^ ((off >> 3) & 0x70);
}

__global__ void __launch_bounds__(256, 2) mma_gemm_kernel(
    const float* __restrict__ scale, float* __restrict__ out)
{
    extern __shared__ __align__(1024) char smem[];
    const uint32_t sb = smem_u32(smem);
    const int tid  = threadIdx.x;
    const int wid  = tid >> 5;
    const int lane = tid & 31;
    const int bm = blockIdx.y * 128;
    const int bn = blockIdx.x * 128;

    const int mbase = (wid >> 2) * 64;      // 0 / 64
    const int nbase = (wid & 3) * 32;       // 0/32/64/96

    auto load_stage = [&](int c, int p) {
        const uint32_t base = sb + p * STAGE;
        const size_t kof = (size_t)c * 64;
#pragma unroll
        for (int it = 0; it < 12; it++) {
            const int id   = tid + it * 256;        // 0..3071
            const int tile = id >> 10;              // 0:Ahi 1:Alo 2:W
            const int rem  = id & 1023;
            const int rw   = rem >> 3;              // row 0..127
            const int c8   = rem & 7;               // 16B chunk
            const uint32_t sa = base + tile * 16384 + swz(rw, c8 * 16);
            const __nv_bfloat16* g =
                (tile == 0) ? g_Ahi + (size_t)(bm + rw) * Ktot + kof + c8 * 8 :
                (tile == 1) ? g_Alo + (size_t)(bm + rw) * Ktot + kof + c8 * 8 :
                              g_Wb  + (size_t)(bn + rw) * Ktot + kof + c8 * 8;
            cp_async16(sa, g);
        }
    };

    float acc[4][4][4];
#pragma unroll
    for (int i = 0; i < 4; i++)
#pragma unroll
        for (int j = 0; j < 4; j++)
#pragma unroll
            for (int q = 0; q < 4; q++) acc[i][j][q] = 0.f;

    const uint32_t rowAl = lane & 15;
    const uint32_t cexA  = (lane >> 4) * 16;
    const uint32_t rowBl = ((lane >> 4) << 3) + (lane & 7);
    const uint32_t cexB  = ((lane >> 3) & 1) * 16;

    load_stage(0, 0);
    CP_COMMIT();

    for (int c = 0; c < NCH; c++) {
        const int p = c & 1;
        if (c + 1 < NCH) {
            load_stage(c + 1, p ^ 1);
            CP_COMMIT();
            CP_WAIT(1);
        } else {
            CP_WAIT(0);
        }
        __syncthreads();

        const uint32_t aB = sb + p * STAGE;          // Ahi
        const uint32_t lB = aB + 16384;               // Alo
        const uint32_t wB = aB + 32768;               // W

#pragma unroll
        for (int ks = 0; ks < 4; ks++) {
            const uint32_t kca = ks * 32 + cexA;
            const uint32_t kcb = ks * 32 + cexB;
            uint32_t bq[4][2];
            {
                uint32_t t[4];
                ldsm_x4(t, wB + swz(nbase + rowBl, kcb));
                bq[0][0] = t[0]; bq[0][1] = t[1]; bq[1][0] = t[2]; bq[1][1] = t[3];
                ldsm_x4(t, wB + swz(nbase + 16 + rowBl, kcb));
                bq[2][0] = t[0]; bq[2][1] = t[1]; bq[3][0] = t[2]; bq[3][1] = t[3];
            }
            uint32_t ah[4][4], al[4][4];
#pragma unroll
            for (int im = 0; im < 4; im++) {
                ldsm_x4(ah[im], aB + swz(mbase + im * 16 + rowAl, kca));
                ldsm_x4(al[im], lB + swz(mbase + im * 16 + rowAl, kca));
            }
#pragma unroll
            for (int im = 0; im < 4; im++)
#pragma unroll
                for (int in = 0; in < 4; in++) {
                    mma_bf16(acc[im][in], ah[im], bq[in]);
                    mma_bf16(acc[im][in], al[im], bq[in]);
                }
        }
        __syncthreads();
    }

    // ---- epilogue ----
    const int gid = lane >> 2;
    const int tig = lane & 3;
#pragma unroll
    for (int in = 0; in < 4; in++) {
        const int col = bn + nbase + in * 8 + tig * 2;
        const float s0 = scale[col], s1 = scale[col + 1];
#pragma unroll
        for (int im = 0; im < 4; im++) {
            const int row0 = bm + mbase + im * 16 + gid;
            float2 o0, o1;
            o0.x = acc[im][in][0] * s0; o0.y = acc[im][in][1] * s1;
            o1.x = acc[im][in][2] * s0; o1.y = acc[im][in][3] * s1;
            *(float2*)&out[(size_t)row0 * Ddim + col]       = o0;
            *(float2*)&out[(size_t)(row0 + 8) * Ddim + col] = o1;
        }
    }
}

// ---------------------------------------------------------------------------
extern "C" void kernel_launch(void* const* d_in, const int* in_sizes, int n_in,
                              void* d_out, int out_size)
{
    const float* r     = (const float*)d_in[0];
    const float* w     = (const float*)d_in[1];
    const float* k     = (const float*)d_in[2];
    const float* v     = (const float*)d_in[3];
    const float* iclr  = (const float*)d_in[4];
    const int*   wq    = (const int*)d_in[5];
    const float* wsc   = (const float*)d_in[6];
    float* out = (float*)d_out;

    static int attr_set = 0;
    if (!attr_set) {
        cudaFuncSetAttribute(mma_gemm_kernel,
                             cudaFuncAttributeMaxDynamicSharedMemorySize, GSM_TOTAL);
        cudaFuncSetAttribute(wkv7_scan_kernel,
                             cudaFuncAttributeMaxDynamicSharedMemorySize, SCAN_SMEM);
        attr_set = 1;
    }

    wkv7_pre_kernel<<<Bdim * Tdim * Hdim / 8, 256>>>(w, k, iclr);
    wconv_kernel<<<(Ddim * Ktot) / 1024, 256>>>(wq);
    wkv7_win_kernel<<<Bdim * Hdim * (Tdim / 4) / 8, 256>>>(k);
    wkv7_scan_kernel<<<Bdim * Hdim, 256, SCAN_SMEM>>>(r, k, v);

    dim3 grid(Ddim / 128, Mtot / 128);
    mma_gemm_kernel<<<grid, 256, GSM_TOTAL>>>(wsc, out);
}

// round 14
// speedup vs baseline: 1.1221x; 1.1221x over previous
#include <cuda_runtime.h>
#include <cuda_bf16.h>
#include <math.h>
#include <stdint.h>

#define Bdim 4
#define Tdim 512
#define Hdim 32
#define Ndim 64
#define Ddim 2048           // Hdim*Ndim
#define Mtot (Bdim*Tdim)    // 2048
#define Ktot Ddim           // 2048

typedef unsigned long long ull;

// ---------------- device scratch (no allocs allowed) ----------------
__device__ float          g_d [Bdim * Tdim * Ddim];   // decay
__device__ float          g_kk[Bdim * Tdim * Ddim];   // qq_m = D_m.kk_m (m>=1), kk_0
__device__ float          g_bb[Bdim * Tdim * Ddim];   // kk * sigmoid(iclr)
__device__ float          g_sc[Bdim * Hdim * (Tdim/4) * 12];  // window scalars
__device__ __nv_bfloat16  g_Ahi[Mtot * Ktot];         // y hi (bf16)
__device__ __nv_bfloat16  g_Alo[Mtot * Ktot];         // y lo (bf16)
__device__ __nv_bfloat16  g_Wb [Ddim * Ktot];         // W (bf16, exact)

// ---------------- PTX helpers (plain sm_80+/sm_100 features only) --------
__device__ __forceinline__ uint32_t smem_u32(const void* p) {
    return (uint32_t)__cvta_generic_to_shared(p);
}
__device__ __forceinline__ void cp_async16(uint32_t smaddr, const void* g) {
    asm volatile("cp.async.cg.shared.global [%0], [%1], 16;" :: "r"(smaddr), "l"(g));
}
#define CP_COMMIT() asm volatile("cp.async.commit_group;" ::: "memory")
#define CP_WAIT(n)  asm volatile("cp.async.wait_group %0;" :: "n"(n) : "memory")

__device__ __forceinline__ void ldsm_x4(uint32_t* r, uint32_t addr) {
    asm volatile("ldmatrix.sync.aligned.m8n8.x4.shared.b16 {%0,%1,%2,%3}, [%4];"
        : "=r"(r[0]), "=r"(r[1]), "=r"(r[2]), "=r"(r[3]) : "r"(addr));
}
__device__ __forceinline__ void mma_bf16(float* d, const uint32_t* a, const uint32_t* b) {
    asm volatile("mma.sync.aligned.m16n8k16.row.col.f32.bf16.bf16.f32 "
        "{%0,%1,%2,%3}, {%4,%5,%6,%7}, {%8,%9}, {%0,%1,%2,%3};"
        : "+f"(d[0]), "+f"(d[1]), "+f"(d[2]), "+f"(d[3])
        : "r"(a[0]), "r"(a[1]), "r"(a[2]), "r"(a[3]), "r"(b[0]), "r"(b[1]));
}

// ---- packed f32x2 (sm_100+ plain PTX) ----
__device__ __forceinline__ ull pack2(float lo, float hi) {
    ull r; asm("mov.b64 %0, {%1, %2};" : "=l"(r) : "f"(lo), "f"(hi)); return r;
}
__device__ __forceinline__ void unpack2(ull v, float& lo, float& hi) {
    asm("mov.b64 {%0, %1}, %2;" : "=f"(lo), "=f"(hi) : "l"(v));
}
__device__ __forceinline__ ull fma2(ull a, ull b, ull c) {
    ull d; asm("fma.rn.f32x2 %0, %1, %2, %3;" : "=l"(d) : "l"(a), "l"(b), "l"(c));
    return d;
}
__device__ __forceinline__ ull mul2(ull a, ull b) {
    ull d; asm("mul.rn.f32x2 %0, %1, %2;" : "=l"(d) : "l"(a), "l"(b)); return d;
}

// ---------------------------------------------------------------------------
// Kernel 0a: merged precompute (decay, kk, b) + window lookahead.
// One warp per 4-step window. Computes d/kk/bb in registers (4 k^2 butterfly
// reduces), writes d, bb, qq_m = D_m.kk_m (kk_0 for m=0), and 12 window
// scalars to g_sc. Replaces the old pre + win kernels (no re-read of d/kk/bb).
// ---------------------------------------------------------------------------
__global__ void __launch_bounds__(256) wkv7_prewin_kernel(
    const float* __restrict__ w, const float* __restrict__ k,
    const float* __restrict__ iclr)
{
    const int win  = blockIdx.x * 8 + (threadIdx.x >> 5);   // 0..16383
    const int lane = threadIdx.x & 31;
    const int ss = win & 127;
    const int h  = (win >> 7) & 31;
    const int b  = win >> 12;
    const int t  = ss * 4;
    const size_t base  = (((size_t)b * Tdim + t) * Hdim + h) * Ndim;
    const size_t tstep = (size_t)Hdim * Ndim;

    float kv[4][2], dm[4][2], sg[4][2], ksum[4];
#pragma unroll
    for (int m = 0; m < 4; m++) {
        ksum[m] = 0.f;
#pragma unroll
        for (int c = 0; c < 2; c++) {
            const size_t idx = base + (size_t)m * tstep + lane + c * 32;
            const float kx = k[idx];
            const float wx = w[idx];
            const float cx = iclr[idx];
            kv[m][c] = kx;
            dm[m][c] = __expf(-__expf(wx));
            sg[m][c] = 1.0f / (1.0f + __expf(-cx));
            ksum[m] = fmaf(kx, kx, ksum[m]);
        }
    }
#pragma unroll
    for (int o = 16; o; o >>= 1)
#pragma unroll
        for (int m = 0; m < 4; m++)
            ksum[m] += __shfl_xor_sync(0xffffffffu, ksum[m], o);

    float inv[4];
#pragma unroll
    for (int m = 0; m < 4; m++) inv[m] = rsqrtf(ksum[m] + 1e-12f);

    float kkm[4][2], bbm[4][2];
#pragma unroll
    for (int m = 0; m < 4; m++)
#pragma unroll
        for (int c = 0; c < 2; c++) {
            kkm[m][c] = kv[m][c] * inv[m];
            bbm[m][c] = kkm[m][c] * sg[m][c];
        }

    float p[12];
#pragma unroll
    for (int i = 0; i < 12; i++) p[i] = 0.f;

#pragma unroll
    for (int c = 0; c < 2; c++) {
        const int j = lane + c * 32;
        const float d0 = dm[0][c], d1 = dm[1][c], d2 = dm[2][c];
        const float D1 = d0, D2 = d0 * d1, D3 = D2 * d2;
        const float qq1 = D1 * kkm[1][c];
        const float qq2 = D2 * kkm[2][c];
        const float qq3 = D3 * kkm[3][c];
        const float e12 = d1, e13 = d1 * d2, e23 = d2;

        p[0]  += bbm[0][c] * kkm[1][c];
        p[1]  += bbm[0][c] * e12 * kkm[2][c];
        p[2]  += bbm[0][c] * e13 * kkm[3][c];
        p[3]  += bbm[1][c] * kkm[2][c];
        p[4]  += bbm[1][c] * e23 * kkm[3][c];
        p[5]  += bbm[2][c] * kkm[3][c];
        p[6]  += kv[0][c] * kkm[1][c];
        p[7]  += kv[0][c] * e12 * kkm[2][c];
        p[8]  += kv[0][c] * e13 * kkm[3][c];
        p[9]  += kv[1][c] * kkm[2][c];
        p[10] += kv[1][c] * e23 * kkm[3][c];
        p[11] += kv[2][c] * kkm[3][c];

        // writes: d (all), bb (all), kk slot: kk_0 / qq_1..3
        g_d[base + j]              = d0;
        g_d[base + tstep + j]      = d1;
        g_d[base + 2 * tstep + j]  = d2;
        g_d[base + 3 * tstep + j]  = dm[3][c];
        g_bb[base + j]             = bbm[0][c];
        g_bb[base + tstep + j]     = bbm[1][c];
        g_bb[base + 2 * tstep + j] = bbm[2][c];
        g_bb[base + 3 * tstep + j] = bbm[3][c];
        g_kk[base + j]             = kkm[0][c];
        g_kk[base + tstep + j]     = qq1;
        g_kk[base + 2 * tstep + j] = qq2;
        g_kk[base + 3 * tstep + j] = qq3;
    }

#pragma unroll
    for (int m = 16; m; m >>= 1)
#pragma unroll
        for (int i = 0; i < 12; i++) p[i] += __shfl_xor_sync(0xffffffffu, p[i], m);

    if (lane == 0) {
        float4* dst = (float4*)&g_sc[(size_t)win * 12];
        dst[0] = make_float4(p[0], p[1], p[2],  p[3]);
        dst[1] = make_float4(p[4], p[5], p[6],  p[7]);
        dst[2] = make_float4(p[8], p[9], p[10], p[11]);
    }
}

// ---------------------------------------------------------------------------
// Kernel 0b: Wq (int32) -> bf16 (exact, |v|<=128)
// ---------------------------------------------------------------------------
__global__ void __launch_bounds__(256) wconv_kernel(const int* __restrict__ wq)
{
    const size_t i4 = (size_t)blockIdx.x * 256 + threadIdx.x;   // int4 index
    int4 q = ((const int4*)wq)[i4];
    __nv_bfloat16 o[4];
    o[0] = __float2bfloat16((float)q.x);
    o[1] = __float2bfloat16((float)q.y);
    o[2] = __float2bfloat16((float)q.z);
    o[3] = __float2bfloat16((float)q.w);
    *(uint2*)&g_Wb[i4 * 4] = *(uint2*)o;
}

// ---------------------------------------------------------------------------
// Kernel 1: WKV scan, 4-step lookahead (R12-exact hot loop), ring deepened to
// 12 slots = 3 windows, prefetch distance 2 windows (wait_group 1).
// ---------------------------------------------------------------------------
#define SLOT_F (6 * Ndim)   // 384 floats per step slot
#define YBUF_F (2 * 4 * 64 * 20)
#define SCAN_SMEM ((12 * SLOT_F + YBUF_F + 36) * 4)

__global__ void __launch_bounds__(256) wkv7_scan_kernel(
    const float* __restrict__ r, const float* __restrict__ k,
    const float* __restrict__ v)
{
    extern __shared__ __align__(16) float dsm[];
    float* sbuf  = dsm;                         // [12][384]
    float* ybuf  = dsm + 12 * SLOT_F;           // [2][4][64][20]
    float* scbuf = ybuf + YBUF_F;               // [3][12]

    const int bh = blockIdx.x;          // 0..127
    const int b  = bh >> 5;
    const int h  = bh & 31;
    const int tid = threadIdx.x;
    const int seg = tid & 15;           // 0..15 (4-col segment)
    const int rp  = tid >> 4;           // 0..15 (row quad)
    const int row0 = rp * 4;
    const int jb  = seg * 4;            // column base
    const int bs0 = seg & 1;
    const int bs1 = (seg >> 1) & 1;
    const int q   = seg & 3;            // owned local row after reduce-scatter

    ull st[4][2];
    const ull zero2 = pack2(0.f, 0.f);
#pragma unroll
    for (int i = 0; i < 4; i++) { st[i][0] = zero2; st[i][1] = zero2; }

    // vector loaders: lanes 0..11 of each warp -> 96 loaders, 1 float4/step
    const int wl   = tid >> 5;
    const int lane = tid & 31;
    const bool is_loader = (lane < 12);
    const int lidx = wl * 12 + lane;        // 0..95
    const int lvec = lidx >> 4;             // 0..5
    const int lq   = lidx & 15;             // 0..15
    const size_t vstep = (size_t)Hdim * Ndim / 4;   // float4 per t

    const float4* gbase = nullptr;
    uint32_t sdst = 0;
    if (is_loader) {
        const float* sp;
        switch (lvec) {
            case 0: sp = g_d;  break;
            case 1: sp = g_kk; break;   // qq
            case 2: sp = g_bb; break;
            case 3: sp = k;    break;
            case 4: sp = r;    break;
            default: sp = v;   break;
        }
        gbase = (const float4*)sp + (((size_t)b * Tdim) * Hdim + h) * (Ndim / 4) + lq;
        sdst  = smem_u32(sbuf) + lidx * 16;
    }
    const uint32_t slot_bytes = SLOT_F * 4;     // 1536

    // scalar loaders: warp 0 lanes 12..14
    const bool is_scl = (tid >= 12 && tid < 15);
    const int  sli    = tid - 12;
    const size_t scgb = (size_t)((b * 32 + h) * 128) * 12;
    const uint32_t scs_base = smem_u32(scbuf);

    // y-reduction mapping (all 256 threads)
    const int ru   = tid >> 6;          // step-in-window 0..3
    const int rrow = tid & 63;          // row
    const size_t ybh = ((size_t)b * Tdim) * Ddim + h * Ndim;

    // prologue: issue windows 0 and 1
#pragma unroll
    for (int pw = 0; pw < 2; pw++) {
        if (is_loader) {
#pragma unroll
            for (int u = 0; u < 4; u++)
                cp_async16(sdst + (pw * 4 + u) * slot_bytes,
                           gbase + (size_t)(pw * 4 + u) * vstep);
        }
        if (is_scl)
            cp_async16(scs_base + pw * 48 + sli * 16,
                       g_sc + scgb + (size_t)pw * 12 + sli * 4);
        CP_COMMIT();
    }

    const int NSS = Tdim / 4;           // 128 windows
    int s0 = 0;                          // ss % 3
    for (int ss = 0; ss < NSS; ss++) {
        const int t0 = ss * 4;
        CP_WAIT(1);                     // window ss landed (issued 2 windows ago)
        __syncthreads();

        // ---- reduce previous window's y partials ----
        if (ss > 0) {
            const float* yb = ybuf + (((ss - 1) & 1) * 4 + ru) * (64 * 20) + rrow * 20;
            float4 a0 = *(const float4*)(yb +  0);
            float4 a1 = *(const float4*)(yb +  4);
            float4 a2 = *(const float4*)(yb +  8);
            float4 a3 = *(const float4*)(yb + 12);
            float s = ((a0.x + a0.y) + (a0.z + a0.w))
                    + ((a1.x + a1.y) + (a1.z + a1.w))
                    + ((a2.x + a2.y) + (a2.z + a2.w))
                    + ((a3.x + a3.y) + (a3.z + a3.w));
            const size_t yi = ybh + (size_t)(t0 - 4 + ru) * Ddim + rrow;
            __nv_bfloat16 hi = __float2bfloat16(s);
            g_Ahi[yi] = hi;
            g_Alo[yi] = __float2bfloat16(s - __bfloat162float(hi));
        }

        // issue window ss+2 into ring slot (ss+2)%3
        int s2 = s0 + 2; if (s2 >= 3) s2 -= 3;
        if (is_loader) {
#pragma unroll
            for (int u = 0; u < 4; u++) {
                const int st4 = t0 + 8 + u;
                if (st4 < Tdim)
                    cp_async16(sdst + (s2 * 4 + u) * slot_bytes,
                               gbase + (size_t)st4 * vstep);
            }
        }
        if (is_scl && (ss + 2 < NSS))
            cp_async16(scs_base + s2 * 48 + sli * 16,
                       g_sc + scgb + (size_t)(ss + 2) * 12 + sli * 4);
        CP_COMMIT();

        // ---- window compute (R12-exact) ----
        const float* sl[4];
#pragma unroll
        for (int m = 0; m < 4; m++) sl[m] = sbuf + ((s0 * 4 + m) * SLOT_F);

        const float4* scp = (const float4*)(scbuf + s0 * 12);
        const float4 sA = scp[0], sB = scp[1], sC = scp[2];
        const float a01 = sA.x, a02 = sA.y, a03 = sA.z, a12 = sA.w;
        const float a13 = sB.x, a23 = sB.y, b01 = sB.z, b02 = sB.w;
        const float b03 = sC.x, b12 = sC.y, b13 = sC.z, b23 = sC.w;

        // 4 dots against base state
        float pd[4][4];
#pragma unroll
        for (int m = 0; m < 4; m++) {
            const ulonglong2 qm = *(const ulonglong2*)(sl[m] + 64 + jb);
#pragma unroll
            for (int i = 0; i < 4; i++) {
                ull pp = fma2(st[i][0], qm.x, mul2(st[i][1], qm.y));
                float plo, phi; unpack2(pp, plo, phi);
                pd[m][i] = plo + phi;
            }
        }

        // merged allreduce: reduce-scatter rows (xor2, xor1), then xor4, xor8
        float u0[4], u1[4], val[4];
#pragma unroll
        for (int m = 0; m < 4; m++) {
            float sendA = bs1 ? pd[m][0] : pd[m][2];
            float sendB = bs1 ? pd[m][1] : pd[m][3];
            float rA = __shfl_xor_sync(0xffffffffu, sendA, 2);
            float rB = __shfl_xor_sync(0xffffffffu, sendB, 2);
            u0[m] = (bs1 ? pd[m][2] : pd[m][0]) + rA;
            u1[m] = (bs1 ? pd[m][3] : pd[m][1]) + rB;
        }
#pragma unroll
        for (int m = 0; m < 4; m++) {
            float send = bs0 ? u0[m] : u1[m];
            float rr = __shfl_xor_sync(0xffffffffu, send, 1);
            val[m] = (bs0 ? u1[m] : u0[m]) + rr;
        }
#pragma unroll
        for (int m = 0; m < 4; m++) val[m] += __shfl_xor_sync(0xffffffffu, val[m], 4);
#pragma unroll
        for (int m = 0; m < 4; m++) val[m] += __shfl_xor_sync(0xffffffffu, val[m], 8);

        // in-lane recurrence for local row q
        const float v0q = sl[0][320 + row0 + q];
        const float v1q = sl[1][320 + row0 + q];
        const float v2q = sl[2][320 + row0 + q];
        float sar[4];
        sar[0] = -val[0];
        sar[1] = -(val[1] + sar[0] * a01 + v0q * b01);
        sar[2] = -(val[2] + sar[0] * a02 + sar[1] * a12 + v0q * b02 + v1q * b12);
        sar[3] = -(val[3] + sar[0] * a03 + sar[1] * a13 + sar[2] * a23
                   + v0q * b03 + v1q * b13 + v2q * b23);

        // allgather rows (xor shfl + selects, R12-exact)
        float gg1[4], gg2[4], gg3[4];
#pragma unroll
        for (int m = 0; m < 4; m++) gg1[m] = __shfl_xor_sync(0xffffffffu, sar[m], 1);
#pragma unroll
        for (int m = 0; m < 4; m++) {
            gg2[m] = __shfl_xor_sync(0xffffffffu, sar[m], 2);
            gg3[m] = __shfl_xor_sync(0xffffffffu, gg1[m], 2);
        }
        float saX[4][4];
#pragma unroll
        for (int m = 0; m < 4; m++) {
            float a01v = bs0 ? gg1[m] : sar[m];
            float a10v = bs0 ? sar[m] : gg1[m];
            float a23v = bs0 ? gg3[m] : gg2[m];
            float a32v = bs0 ? gg2[m] : gg3[m];
            saX[m][0] = bs1 ? a23v : a01v;
            saX[m][1] = bs1 ? a32v : a10v;
            saX[m][2] = bs1 ? a01v : a23v;
            saX[m][3] = bs1 ? a10v : a32v;
        }

        // 4 state updates + deferred y partials
        float* ywb = ybuf + ((ss & 1) * 4) * (64 * 20);
#pragma unroll
        for (int m = 0; m < 4; m++) {
            const float* s = sl[m];
            const ulonglong2 dv = *(const ulonglong2*)(s +   0 + jb);
            const ulonglong2 bv = *(const ulonglong2*)(s + 128 + jb);
            const ulonglong2 kv = *(const ulonglong2*)(s + 192 + jb);
            const ulonglong2 rv = *(const ulonglong2*)(s + 256 + jb);
            const float4 vv4 = *(const float4*)(s + 320 + row0);
            const float varr[4] = {vv4.x, vv4.y, vv4.z, vv4.w};
            float* yw = ywb + m * (64 * 20);
#pragma unroll
            for (int i = 0; i < 4; i++) {
                const ull sa2 = pack2(saX[m][i], saX[m][i]);
                const ull v2  = pack2(varr[i], varr[i]);
                st[i][0] = fma2(st[i][0], dv.x, fma2(sa2, bv.x, mul2(v2, kv.x)));
                st[i][1] = fma2(st[i][1], dv.y, fma2(sa2, bv.y, mul2(v2, kv.y)));
                ull ya = fma2(st[i][0], rv.x, fma2(st[i][1], rv.y, zero2));
                float ylo, yhi; unpack2(ya, ylo, yhi);
                yw[(row0 + i) * 20 + seg] = ylo + yhi;
            }
        }

        s0 = (s0 + 1 == 3) ? 0 : s0 + 1;
    }

    // tail: reduce the last window's y
    __syncthreads();
    {
        const float* yb = ybuf + (((NSS - 1) & 1) * 4 + ru) * (64 * 20) + rrow * 20;
        float4 a0 = *(const float4*)(yb +  0);
        float4 a1 = *(const float4*)(yb +  4);
        float4 a2 = *(const float4*)(yb +  8);
        float4 a3 = *(const float4*)(yb + 12);
        float s = ((a0.x + a0.y) + (a0.z + a0.w))
                + ((a1.x + a1.y) + (a1.z + a1.w))
                + ((a2.x + a2.y) + (a2.z + a2.w))
                + ((a3.x + a3.y) + (a3.z + a3.w));
        const size_t yi = ybh + (size_t)(Tdim - 4 + ru) * Ddim + rrow;
        __nv_bfloat16 hi = __float2bfloat16(s);
        g_Ahi[yi] = hi;
        g_Alo[yi] = __float2bfloat16(s - __bfloat162float(hi));
    }
}

// ---------------------------------------------------------------------------
// Kernel 2: mma.sync bf16 split GEMM (NT). 2-stage, 96KB (R10/R12 exact).
// ---------------------------------------------------------------------------
#define NCH   (Ktot / 64)          // 32 K-chunks
#define STAGE 49152                // 3 tiles * 16KB
#define GSM_TOTAL (2 * STAGE)

__device__ __forceinline__ uint32_t swz(uint32_t row, uint32_t cbyte) {
    uint32_t off = row * 128 + cbyte;
    return off ^ ((off >> 3) & 0x70);
}

__global__ void __launch_bounds__(256, 2) mma_gemm_kernel(
    const float* __restrict__ scale, float* __restrict__ out)
{
    extern __shared__ __align__(1024) char smem[];
    const uint32_t sb = smem_u32(smem);
    const int tid  = threadIdx.x;
    const int wid  = tid >> 5;
    const int lane = tid & 31;
    const int bm = blockIdx.y * 128;
    const int bn = blockIdx.x * 128;

    const int mbase = (wid >> 2) * 64;      // 0 / 64
    const int nbase = (wid & 3) * 32;       // 0/32/64/96

    auto load_stage = [&](int c, int p) {
        const uint32_t base = sb + p * STAGE;
        const size_t kof = (size_t)c * 64;
#pragma unroll
        for (int it = 0; it < 12; it++) {
            const int id   = tid + it * 256;        // 0..3071
            const int tile = id >> 10;              // 0:Ahi 1:Alo 2:W
            const int rem  = id & 1023;
            const int rw   = rem >> 3;              // row 0..127
            const int c8   = rem & 7;               // 16B chunk
            const uint32_t sa = base + tile * 16384 + swz(rw, c8 * 16);
            const __nv_bfloat16* g =
                (tile == 0) ? g_Ahi + (size_t)(bm + rw) * Ktot + kof + c8 * 8 :
                (tile == 1) ? g_Alo + (size_t)(bm + rw) * Ktot + kof + c8 * 8 :
                              g_Wb  + (size_t)(bn + rw) * Ktot + kof + c8 * 8;
            cp_async16(sa, g);
        }
    };

    float acc[4][4][4];
#pragma unroll
    for (int i = 0; i < 4; i++)
#pragma unroll
        for (int j = 0; j < 4; j++)
#pragma unroll
            for (int q = 0; q < 4; q++) acc[i][j][q] = 0.f;

    const uint32_t rowAl = lane & 15;
    const uint32_t cexA  = (lane >> 4) * 16;
    const uint32_t rowBl = ((lane >> 4) << 3) + (lane & 7);
    const uint32_t cexB  = ((lane >> 3) & 1) * 16;

    load_stage(0, 0);
    CP_COMMIT();

    for (int c = 0; c < NCH; c++) {
        const int p = c & 1;
        if (c + 1 < NCH) {
            load_stage(c + 1, p ^ 1);
            CP_COMMIT();
            CP_WAIT(1);
        } else {
            CP_WAIT(0);
        }
        __syncthreads();

        const uint32_t aB = sb + p * STAGE;          // Ahi
        const uint32_t lB = aB + 16384;               // Alo
        const uint32_t wB = aB + 32768;               // W

#pragma unroll
        for (int ks = 0; ks < 4; ks++) {
            const uint32_t kca = ks * 32 + cexA;
            const uint32_t kcb = ks * 32 + cexB;
            uint32_t bq[4][2];
            {
                uint32_t t[4];
                ldsm_x4(t, wB + swz(nbase + rowBl, kcb));
                bq[0][0] = t[0]; bq[0][1] = t[1]; bq[1][0] = t[2]; bq[1][1] = t[3];
                ldsm_x4(t, wB + swz(nbase + 16 + rowBl, kcb));
                bq[2][0] = t[0]; bq[2][1] = t[1]; bq[3][0] = t[2]; bq[3][1] = t[3];
            }
            uint32_t ah[4][4], al[4][4];
#pragma unroll
            for (int im = 0; im < 4; im++) {
                ldsm_x4(ah[im], aB + swz(mbase + im * 16 + rowAl, kca));
                ldsm_x4(al[im], lB + swz(mbase + im * 16 + rowAl, kca));
            }
#pragma unroll
            for (int im = 0; im < 4; im++)
#pragma unroll
                for (int in = 0; in < 4; in++) {
                    mma_bf16(acc[im][in], ah[im], bq[in]);
                    mma_bf16(acc[im][in], al[im], bq[in]);
                }
        }
        __syncthreads();
    }

    // ---- epilogue ----
    const int gid = lane >> 2;
    const int tig = lane & 3;
#pragma unroll
    for (int in = 0; in < 4; in++) {
        const int col = bn + nbase + in * 8 + tig * 2;
        const float s0 = scale[col], s1 = scale[col + 1];
#pragma unroll
        for (int im = 0; im < 4; im++) {
            const int row0 = bm + mbase + im * 16 + gid;
            float2 o0, o1;
            o0.x = acc[im][in][0] * s0; o0.y = acc[im][in][1] * s1;
            o1.x = acc[im][in][2] * s0; o1.y = acc[im][in][3] * s1;
            *(float2*)&out[(size_t)row0 * Ddim + col]       = o0;
            *(float2*)&out[(size_t)(row0 + 8) * Ddim + col] = o1;
        }
    }
}

// ---------------------------------------------------------------------------
extern "C" void kernel_launch(void* const* d_in, const int* in_sizes, int n_in,
                              void* d_out, int out_size)
{
    const float* r     = (const float*)d_in[0];
    const float* w     = (const float*)d_in[1];
    const float* k     = (const float*)d_in[2];
    const float* v     = (const float*)d_in[3];
    const float* iclr  = (const float*)d_in[4];
    const int*   wq    = (const int*)d_in[5];
    const float* wsc   = (const float*)d_in[6];
    float* out = (float*)d_out;

    static int attr_set = 0;
    if (!attr_set) {
        cudaFuncSetAttribute(mma_gemm_kernel,
                             cudaFuncAttributeMaxDynamicSharedMemorySize, GSM_TOTAL);
        cudaFuncSetAttribute(wkv7_scan_kernel,
                             cudaFuncAttributeMaxDynamicSharedMemorySize, SCAN_SMEM);
        attr_set = 1;
    }

    wkv7_prewin_kernel<<<Bdim * Hdim * (Tdim / 4) / 8, 256>>>(w, k, iclr);
    wconv_kernel<<<(Ddim * Ktot) / 1024, 256>>>(wq);
    wkv7_scan_kernel<<<Bdim * Hdim, 256, SCAN_SMEM>>>(r, k, v);

    dim3 grid(Ddim / 128, Mtot / 128);
    mma_gemm_kernel<<<grid, 256, GSM_TOTAL>>>(wsc, out);
}

// round 15
// speedup vs baseline: 1.3469x; 1.2004x over previous
#include <cuda_runtime.h>
#include <cuda_bf16.h>
#include <cuda_fp16.h>
#include <math.h>
#include <stdint.h>

#define Bdim 4
#define Tdim 512
#define Hdim 32
#define Ndim 64
#define Ddim 2048           // Hdim*Ndim
#define Mtot (Bdim*Tdim)    // 2048
#define Ktot Ddim           // 2048

typedef unsigned long long ull;

// ---------------- device scratch (no allocs allowed) ----------------
__device__ float   g_d [Bdim * Tdim * Ddim];   // decay
__device__ float   g_kk[Bdim * Tdim * Ddim];   // qq_m = D_m.kk_m (m>=1), kk_0
__device__ float   g_bb[Bdim * Tdim * Ddim];   // kk * sigmoid(iclr)
__device__ float   g_sc[Bdim * Hdim * (Tdim/4) * 12];  // window scalars
__device__ __half  g_Af[Mtot * Ktot];          // y (fp16)
__device__ __half  g_Wh[Ddim * Ktot];          // W (fp16, exact: ints <= 128)

// ---------------- PTX helpers (plain sm_80+/sm_100 features only) --------
__device__ __forceinline__ uint32_t smem_u32(const void* p) {
    return (uint32_t)__cvta_generic_to_shared(p);
}
__device__ __forceinline__ void cp_async16(uint32_t smaddr, const void* g) {
    asm volatile("cp.async.cg.shared.global [%0], [%1], 16;" :: "r"(smaddr), "l"(g));
}
#define CP_COMMIT() asm volatile("cp.async.commit_group;" ::: "memory")
#define CP_WAIT(n)  asm volatile("cp.async.wait_group %0;" :: "n"(n) : "memory")

__device__ __forceinline__ void ldsm_x4(uint32_t* r, uint32_t addr) {
    asm volatile("ldmatrix.sync.aligned.m8n8.x4.shared.b16 {%0,%1,%2,%3}, [%4];"
        : "=r"(r[0]), "=r"(r[1]), "=r"(r[2]), "=r"(r[3]) : "r"(addr));
}
__device__ __forceinline__ void mma_f16(float* d, const uint32_t* a, const uint32_t* b) {
    asm volatile("mma.sync.aligned.m16n8k16.row.col.f32.f16.f16.f32 "
        "{%0,%1,%2,%3}, {%4,%5,%6,%7}, {%8,%9}, {%0,%1,%2,%3};"
        : "+f"(d[0]), "+f"(d[1]), "+f"(d[2]), "+f"(d[3])
        : "r"(a[0]), "r"(a[1]), "r"(a[2]), "r"(a[3]), "r"(b[0]), "r"(b[1]));
}

// ---- packed f32x2 (sm_100+ plain PTX) ----
__device__ __forceinline__ ull pack2(float lo, float hi) {
    ull r; asm("mov.b64 %0, {%1, %2};" : "=l"(r) : "f"(lo), "f"(hi)); return r;
}
__device__ __forceinline__ void unpack2(ull v, float& lo, float& hi) {
    asm("mov.b64 {%0, %1}, %2;" : "=f"(lo), "=f"(hi) : "l"(v));
}
__device__ __forceinline__ ull fma2(ull a, ull b, ull c) {
    ull d; asm("fma.rn.f32x2 %0, %1, %2, %3;" : "=l"(d) : "l"(a), "l"(b), "l"(c));
    return d;
}
__device__ __forceinline__ ull mul2(ull a, ull b) {
    ull d; asm("mul.rn.f32x2 %0, %1, %2;" : "=l"(d) : "l"(a), "l"(b)); return d;
}

// ---------------------------------------------------------------------------
// Kernel 0a: merged precompute (decay, kk, b) + window lookahead.
// One warp per 4-step window (R14-exact).
// ---------------------------------------------------------------------------
__global__ void __launch_bounds__(256) wkv7_prewin_kernel(
    const float* __restrict__ w, const float* __restrict__ k,
    const float* __restrict__ iclr)
{
    const int win  = blockIdx.x * 8 + (threadIdx.x >> 5);   // 0..16383
    const int lane = threadIdx.x & 31;
    const int ss = win & 127;
    const int h  = (win >> 7) & 31;
    const int b  = win >> 12;
    const int t  = ss * 4;
    const size_t base  = (((size_t)b * Tdim + t) * Hdim + h) * Ndim;
    const size_t tstep = (size_t)Hdim * Ndim;

    float kv[4][2], dm[4][2], sg[4][2], ksum[4];
#pragma unroll
    for (int m = 0; m < 4; m++) {
        ksum[m] = 0.f;
#pragma unroll
        for (int c = 0; c < 2; c++) {
            const size_t idx = base + (size_t)m * tstep + lane + c * 32;
            const float kx = k[idx];
            const float wx = w[idx];
            const float cx = iclr[idx];
            kv[m][c] = kx;
            dm[m][c] = __expf(-__expf(wx));
            sg[m][c] = 1.0f / (1.0f + __expf(-cx));
            ksum[m] = fmaf(kx, kx, ksum[m]);
        }
    }
#pragma unroll
    for (int o = 16; o; o >>= 1)
#pragma unroll
        for (int m = 0; m < 4; m++)
            ksum[m] += __shfl_xor_sync(0xffffffffu, ksum[m], o);

    float inv[4];
#pragma unroll
    for (int m = 0; m < 4; m++) inv[m] = rsqrtf(ksum[m] + 1e-12f);

    float kkm[4][2], bbm[4][2];
#pragma unroll
    for (int m = 0; m < 4; m++)
#pragma unroll
        for (int c = 0; c < 2; c++) {
            kkm[m][c] = kv[m][c] * inv[m];
            bbm[m][c] = kkm[m][c] * sg[m][c];
        }

    float p[12];
#pragma unroll
    for (int i = 0; i < 12; i++) p[i] = 0.f;

#pragma unroll
    for (int c = 0; c < 2; c++) {
        const int j = lane + c * 32;
        const float d0 = dm[0][c], d1 = dm[1][c], d2 = dm[2][c];
        const float D1 = d0, D2 = d0 * d1, D3 = D2 * d2;
        const float qq1 = D1 * kkm[1][c];
        const float qq2 = D2 * kkm[2][c];
        const float qq3 = D3 * kkm[3][c];
        const float e12 = d1, e13 = d1 * d2, e23 = d2;

        p[0]  += bbm[0][c] * kkm[1][c];
        p[1]  += bbm[0][c] * e12 * kkm[2][c];
        p[2]  += bbm[0][c] * e13 * kkm[3][c];
        p[3]  += bbm[1][c] * kkm[2][c];
        p[4]  += bbm[1][c] * e23 * kkm[3][c];
        p[5]  += bbm[2][c] * kkm[3][c];
        p[6]  += kv[0][c] * kkm[1][c];
        p[7]  += kv[0][c] * e12 * kkm[2][c];
        p[8]  += kv[0][c] * e13 * kkm[3][c];
        p[9]  += kv[1][c] * kkm[2][c];
        p[10] += kv[1][c] * e23 * kkm[3][c];
        p[11] += kv[2][c] * kkm[3][c];

        g_d[base + j]              = d0;
        g_d[base + tstep + j]      = d1;
        g_d[base + 2 * tstep + j]  = d2;
        g_d[base + 3 * tstep + j]  = dm[3][c];
        g_bb[base + j]             = bbm[0][c];
        g_bb[base + tstep + j]     = bbm[1][c];
        g_bb[base + 2 * tstep + j] = bbm[2][c];
        g_bb[base + 3 * tstep + j] = bbm[3][c];
        g_kk[base + j]             = kkm[0][c];
        g_kk[base + tstep + j]     = qq1;
        g_kk[base + 2 * tstep + j] = qq2;
        g_kk[base + 3 * tstep + j] = qq3;
    }

#pragma unroll
    for (int m = 16; m; m >>= 1)
#pragma unroll
        for (int i = 0; i < 12; i++) p[i] += __shfl_xor_sync(0xffffffffu, p[i], m);

    if (lane == 0) {
        float4* dst = (float4*)&g_sc[(size_t)win * 12];
        dst[0] = make_float4(p[0], p[1], p[2],  p[3]);
        dst[1] = make_float4(p[4], p[5], p[6],  p[7]);
        dst[2] = make_float4(p[8], p[9], p[10], p[11]);
    }
}

// ---------------------------------------------------------------------------
// Kernel 0b: Wq (int32) -> fp16 (exact, |v|<=128)
// ---------------------------------------------------------------------------
__global__ void __launch_bounds__(256) wconv_kernel(const int* __restrict__ wq)
{
    const size_t i4 = (size_t)blockIdx.x * 256 + threadIdx.x;   // int4 index
    int4 q = ((const int4*)wq)[i4];
    __half o[4];
    o[0] = __int2half_rn(q.x);
    o[1] = __int2half_rn(q.y);
    o[2] = __int2half_rn(q.z);
    o[3] = __int2half_rn(q.w);
    *(uint2*)&g_Wh[i4 * 4] = *(uint2*)o;
}

// ---------------------------------------------------------------------------
// Kernel 1: WKV scan, 4-step lookahead (R14-exact hot loop), y -> fp16.
// 12-slot ring (3 windows), prefetch distance 2 (wait_group 1).
// ---------------------------------------------------------------------------
#define SLOT_F (6 * Ndim)   // 384 floats per step slot
#define YBUF_F (2 * 4 * 64 * 20)
#define SCAN_SMEM ((12 * SLOT_F + YBUF_F + 36) * 4)

__global__ void __launch_bounds__(256) wkv7_scan_kernel(
    const float* __restrict__ r, const float* __restrict__ k,
    const float* __restrict__ v)
{
    extern __shared__ __align__(16) float dsm[];
    float* sbuf  = dsm;                         // [12][384]
    float* ybuf  = dsm + 12 * SLOT_F;           // [2][4][64][20]
    float* scbuf = ybuf + YBUF_F;               // [3][12]

    const int bh = blockIdx.x;          // 0..127
    const int b  = bh >> 5;
    const int h  = bh & 31;
    const int tid = threadIdx.x;
    const int seg = tid & 15;           // 0..15 (4-col segment)
    const int rp  = tid >> 4;           // 0..15 (row quad)
    const int row0 = rp * 4;
    const int jb  = seg * 4;            // column base
    const int bs0 = seg & 1;
    const int bs1 = (seg >> 1) & 1;
    const int q   = seg & 3;            // owned local row after reduce-scatter

    ull st[4][2];
    const ull zero2 = pack2(0.f, 0.f);
#pragma unroll
    for (int i = 0; i < 4; i++) { st[i][0] = zero2; st[i][1] = zero2; }

    // vector loaders: lanes 0..11 of each warp -> 96 loaders, 1 float4/step
    const int wl   = tid >> 5;
    const int lane = tid & 31;
    const bool is_loader = (lane < 12);
    const int lidx = wl * 12 + lane;        // 0..95
    const int lvec = lidx >> 4;             // 0..5
    const int lq   = lidx & 15;             // 0..15
    const size_t vstep = (size_t)Hdim * Ndim / 4;   // float4 per t

    const float4* gbase = nullptr;
    uint32_t sdst = 0;
    if (is_loader) {
        const float* sp;
        switch (lvec) {
            case 0: sp = g_d;  break;
            case 1: sp = g_kk; break;   // qq
            case 2: sp = g_bb; break;
            case 3: sp = k;    break;
            case 4: sp = r;    break;
            default: sp = v;   break;
        }
        gbase = (const float4*)sp + (((size_t)b * Tdim) * Hdim + h) * (Ndim / 4) + lq;
        sdst  = smem_u32(sbuf) + lidx * 16;
    }
    const uint32_t slot_bytes = SLOT_F * 4;     // 1536

    // scalar loaders: warp 0 lanes 12..14
    const bool is_scl = (tid >= 12 && tid < 15);
    const int  sli    = tid - 12;
    const size_t scgb = (size_t)((b * 32 + h) * 128) * 12;
    const uint32_t scs_base = smem_u32(scbuf);

    // y-reduction mapping (all 256 threads)
    const int ru   = tid >> 6;          // step-in-window 0..3
    const int rrow = tid & 63;          // row
    const size_t ybh = ((size_t)b * Tdim) * Ddim + h * Ndim;

    // prologue: issue windows 0 and 1
#pragma unroll
    for (int pw = 0; pw < 2; pw++) {
        if (is_loader) {
#pragma unroll
            for (int u = 0; u < 4; u++)
                cp_async16(sdst + (pw * 4 + u) * slot_bytes,
                           gbase + (size_t)(pw * 4 + u) * vstep);
        }
        if (is_scl)
            cp_async16(scs_base + pw * 48 + sli * 16,
                       g_sc + scgb + (size_t)pw * 12 + sli * 4);
        CP_COMMIT();
    }

    const int NSS = Tdim / 4;           // 128 windows
    int s0 = 0;                          // ss % 3
    for (int ss = 0; ss < NSS; ss++) {
        const int t0 = ss * 4;
        CP_WAIT(1);                     // window ss landed (issued 2 windows ago)
        __syncthreads();

        // ---- reduce previous window's y partials ----
        if (ss > 0) {
            const float* yb = ybuf + (((ss - 1) & 1) * 4 + ru) * (64 * 20) + rrow * 20;
            float4 a0 = *(const float4*)(yb +  0);
            float4 a1 = *(const float4*)(yb +  4);
            float4 a2 = *(const float4*)(yb +  8);
            float4 a3 = *(const float4*)(yb + 12);
            float s = ((a0.x + a0.y) + (a0.z + a0.w))
                    + ((a1.x + a1.y) + (a1.z + a1.w))
                    + ((a2.x + a2.y) + (a2.z + a2.w))
                    + ((a3.x + a3.y) + (a3.z + a3.w));
            const size_t yi = ybh + (size_t)(t0 - 4 + ru) * Ddim + rrow;
            g_Af[yi] = __float2half(s);
        }

        // issue window ss+2 into ring slot (ss+2)%3
        int s2 = s0 + 2; if (s2 >= 3) s2 -= 3;
        if (is_loader) {
#pragma unroll
            for (int u = 0; u < 4; u++) {
                const int st4 = t0 + 8 + u;
                if (st4 < Tdim)
                    cp_async16(sdst + (s2 * 4 + u) * slot_bytes,
                               gbase + (size_t)st4 * vstep);
            }
        }
        if (is_scl && (ss + 2 < NSS))
            cp_async16(scs_base + s2 * 48 + sli * 16,
                       g_sc + scgb + (size_t)(ss + 2) * 12 + sli * 4);
        CP_COMMIT();

        // ---- window compute (R12/R14-exact) ----
        const float* sl[4];
#pragma unroll
        for (int m = 0; m < 4; m++) sl[m] = sbuf + ((s0 * 4 + m) * SLOT_F);

        const float4* scp = (const float4*)(scbuf + s0 * 12);
        const float4 sA = scp[0], sB = scp[1], sC = scp[2];
        const float a01 = sA.x, a02 = sA.y, a03 = sA.z, a12 = sA.w;
        const float a13 = sB.x, a23 = sB.y, b01 = sB.z, b02 = sB.w;
        const float b03 = sC.x, b12 = sC.y, b13 = sC.z, b23 = sC.w;

        // 4 dots against base state
        float pd[4][4];
#pragma unroll
        for (int m = 0; m < 4; m++) {
            const ulonglong2 qm = *(const ulonglong2*)(sl[m] + 64 + jb);
#pragma unroll
            for (int i = 0; i < 4; i++) {
                ull pp = fma2(st[i][0], qm.x, mul2(st[i][1], qm.y));
                float plo, phi; unpack2(pp, plo, phi);
                pd[m][i] = plo + phi;
            }
        }

        // merged allreduce: reduce-scatter rows (xor2, xor1), then xor4, xor8
        float u0[4], u1[4], val[4];
#pragma unroll
        for (int m = 0; m < 4; m++) {
            float sendA = bs1 ? pd[m][0] : pd[m][2];
            float sendB = bs1 ? pd[m][1] : pd[m][3];
            float rA = __shfl_xor_sync(0xffffffffu, sendA, 2);
            float rB = __shfl_xor_sync(0xffffffffu, sendB, 2);
            u0[m] = (bs1 ? pd[m][2] : pd[m][0]) + rA;
            u1[m] = (bs1 ? pd[m][3] : pd[m][1]) + rB;
        }
#pragma unroll
        for (int m = 0; m < 4; m++) {
            float send = bs0 ? u0[m] : u1[m];
            float rr = __shfl_xor_sync(0xffffffffu, send, 1);
            val[m] = (bs0 ? u1[m] : u0[m]) + rr;
        }
#pragma unroll
        for (int m = 0; m < 4; m++) val[m] += __shfl_xor_sync(0xffffffffu, val[m], 4);
#pragma unroll
        for (int m = 0; m < 4; m++) val[m] += __shfl_xor_sync(0xffffffffu, val[m], 8);

        // in-lane recurrence for local row q
        const float v0q = sl[0][320 + row0 + q];
        const float v1q = sl[1][320 + row0 + q];
        const float v2q = sl[2][320 + row0 + q];
        float sar[4];
        sar[0] = -val[0];
        sar[1] = -(val[1] + sar[0] * a01 + v0q * b01);
        sar[2] = -(val[2] + sar[0] * a02 + sar[1] * a12 + v0q * b02 + v1q * b12);
        sar[3] = -(val[3] + sar[0] * a03 + sar[1] * a13 + sar[2] * a23
                   + v0q * b03 + v1q * b13 + v2q * b23);

        // allgather rows (xor shfl + selects)
        float gg1[4], gg2[4], gg3[4];
#pragma unroll
        for (int m = 0; m < 4; m++) gg1[m] = __shfl_xor_sync(0xffffffffu, sar[m], 1);
#pragma unroll
        for (int m = 0; m < 4; m++) {
            gg2[m] = __shfl_xor_sync(0xffffffffu, sar[m], 2);
            gg3[m] = __shfl_xor_sync(0xffffffffu, gg1[m], 2);
        }
        float saX[4][4];
#pragma unroll
        for (int m = 0; m < 4; m++) {
            float a01v = bs0 ? gg1[m] : sar[m];
            float a10v = bs0 ? sar[m] : gg1[m];
            float a23v = bs0 ? gg3[m] : gg2[m];
            float a32v = bs0 ? gg2[m] : gg3[m];
            saX[m][0] = bs1 ? a23v : a01v;
            saX[m][1] = bs1 ? a32v : a10v;
            saX[m][2] = bs1 ? a01v : a23v;
            saX[m][3] = bs1 ? a10v : a32v;
        }

        // 4 state updates + deferred y partials
        float* ywb = ybuf + ((ss & 1) * 4) * (64 * 20);
#pragma unroll
        for (int m = 0; m < 4; m++) {
            const float* s = sl[m];
            const ulonglong2 dv = *(const ulonglong2*)(s +   0 + jb);
            const ulonglong2 bv = *(const ulonglong2*)(s + 128 + jb);
            const ulonglong2 kv = *(const ulonglong2*)(s + 192 + jb);
            const ulonglong2 rv = *(const ulonglong2*)(s + 256 + jb);
            const float4 vv4 = *(const float4*)(s + 320 + row0);
            const float varr[4] = {vv4.x, vv4.y, vv4.z, vv4.w};
            float* yw = ywb + m * (64 * 20);
#pragma unroll
            for (int i = 0; i < 4; i++) {
                const ull sa2 = pack2(saX[m][i], saX[m][i]);
                const ull v2  = pack2(varr[i], varr[i]);
                st[i][0] = fma2(st[i][0], dv.x, fma2(sa2, bv.x, mul2(v2, kv.x)));
                st[i][1] = fma2(st[i][1], dv.y, fma2(sa2, bv.y, mul2(v2, kv.y)));
                ull ya = fma2(st[i][0], rv.x, fma2(st[i][1], rv.y, zero2));
                float ylo, yhi; unpack2(ya, ylo, yhi);
                yw[(row0 + i) * 20 + seg] = ylo + yhi;
            }
        }

        s0 = (s0 + 1 == 3) ? 0 : s0 + 1;
    }

    // tail: reduce the last window's y
    __syncthreads();
    {
        const float* yb = ybuf + (((NSS - 1) & 1) * 4 + ru) * (64 * 20) + rrow * 20;
        float4 a0 = *(const float4*)(yb +  0);
        float4 a1 = *(const float4*)(yb +  4);
        float4 a2 = *(const float4*)(yb +  8);
        float4 a3 = *(const float4*)(yb + 12);
        float s = ((a0.x + a0.y) + (a0.z + a0.w))
                + ((a1.x + a1.y) + (a1.z + a1.w))
                + ((a2.x + a2.y) + (a2.z + a2.w))
                + ((a3.x + a3.y) + (a3.z + a3.w));
        const size_t yi = ybh + (size_t)(Tdim - 4 + ru) * Ddim + rrow;
        g_Af[yi] = __float2half(s);
    }
}

// ---------------------------------------------------------------------------
// Kernel 2: mma.sync fp16 single-stream GEMM (NT). 2-stage, 64KB total.
// 128x128 tile, BK=64, 8 warps (2x4), warp tile 64x32, SW128 swizzle.
// out[m,o] = scale[o] * A[m,:] . Wh[o,:]
// ---------------------------------------------------------------------------
#define NCH   (Ktot / 64)          // 32 K-chunks
#define STAGE 32768                // 2 tiles * 16KB
#define GSM_TOTAL (2 * STAGE)

__device__ __forceinline__ uint32_t swz(uint32_t row, uint32_t cbyte) {
    uint32_t off = row * 128 + cbyte;
    return off ^ ((off >> 3) & 0x70);
}

__global__ void __launch_bounds__(256, 2) mma_gemm_kernel(
    const float* __restrict__ scale, float* __restrict__ out)
{
    extern __shared__ __align__(1024) char smem[];
    const uint32_t sb = smem_u32(smem);
    const int tid  = threadIdx.x;
    const int wid  = tid >> 5;
    const int lane = tid & 31;
    const int bm = blockIdx.y * 128;
    const int bn = blockIdx.x * 128;

    const int mbase = (wid >> 2) * 64;      // 0 / 64
    const int nbase = (wid & 3) * 32;       // 0/32/64/96

    auto load_stage = [&](int c, int p) {
        const uint32_t base = sb + p * STAGE;
        const size_t kof = (size_t)c * 64;
#pragma unroll
        for (int it = 0; it < 8; it++) {
            const int id   = tid + it * 256;        // 0..2047
            const int tile = id >> 10;              // 0:A 1:W
            const int rem  = id & 1023;
            const int rw   = rem >> 3;              // row 0..127
            const int c8   = rem & 7;               // 16B chunk
            const uint32_t sa = base + tile * 16384 + swz(rw, c8 * 16);
            const __half* g =
                (tile == 0) ? g_Af + (size_t)(bm + rw) * Ktot + kof + c8 * 8
                            : g_Wh + (size_t)(bn + rw) * Ktot + kof + c8 * 8;
            cp_async16(sa, g);
        }
    };

    float acc[4][4][4];
#pragma unroll
    for (int i = 0; i < 4; i++)
#pragma unroll
        for (int j = 0; j < 4; j++)
#pragma unroll
            for (int q = 0; q < 4; q++) acc[i][j][q] = 0.f;

    const uint32_t rowAl = lane & 15;
    const uint32_t cexA  = (lane >> 4) * 16;
    const uint32_t rowBl = ((lane >> 4) << 3) + (lane & 7);
    const uint32_t cexB  = ((lane >> 3) & 1) * 16;

    load_stage(0, 0);
    CP_COMMIT();

    for (int c = 0; c < NCH; c++) {
        const int p = c & 1;
        if (c + 1 < NCH) {
            load_stage(c + 1, p ^ 1);
            CP_COMMIT();
            CP_WAIT(1);
        } else {
            CP_WAIT(0);
        }
        __syncthreads();

        const uint32_t aB = sb + p * STAGE;          // A
        const uint32_t wB = aB + 16384;               // W

#pragma unroll
        for (int ks = 0; ks < 4; ks++) {
            const uint32_t kca = ks * 32 + cexA;
            const uint32_t kcb = ks * 32 + cexB;
            uint32_t bq[4][2];
            {
                uint32_t t[4];
                ldsm_x4(t, wB + swz(nbase + rowBl, kcb));
                bq[0][0] = t[0]; bq[0][1] = t[1]; bq[1][0] = t[2]; bq[1][1] = t[3];
                ldsm_x4(t, wB + swz(nbase + 16 + rowBl, kcb));
                bq[2][0] = t[0]; bq[2][1] = t[1]; bq[3][0] = t[2]; bq[3][1] = t[3];
            }
            uint32_t ah[4][4];
#pragma unroll
            for (int im = 0; im < 4; im++)
                ldsm_x4(ah[im], aB + swz(mbase + im * 16 + rowAl, kca));
#pragma unroll
            for (int im = 0; im < 4; im++)
#pragma unroll
                for (int in = 0; in < 4; in++)
                    mma_f16(acc[im][in], ah[im], bq[in]);
        }
        __syncthreads();
    }

    // ---- epilogue ----
    const int gid = lane >> 2;
    const int tig = lane & 3;
#pragma unroll
    for (int in = 0; in < 4; in++) {
        const int col = bn + nbase + in * 8 + tig * 2;
        const float s0 = scale[col], s1 = scale[col + 1];
#pragma unroll
        for (int im = 0; im < 4; im++) {
            const int row0 = bm + mbase + im * 16 + gid;
            float2 o0, o1;
            o0.x = acc[im][in][0] * s0; o0.y = acc[im][in][1] * s1;
            o1.x = acc[im][in][2] * s0; o1.y = acc[im][in][3] * s1;
            *(float2*)&out[(size_t)row0 * Ddim + col]       = o0;
            *(float2*)&out[(size_t)(row0 + 8) * Ddim + col] = o1;
        }
    }
}

// ---------------------------------------------------------------------------
extern "C" void kernel_launch(void* const* d_in, const int* in_sizes, int n_in,
                              void* d_out, int out_size)
{
    const float* r     = (const float*)d_in[0];
    const float* w     = (const float*)d_in[1];
    const float* k     = (const float*)d_in[2];
    const float* v     = (const float*)d_in[3];
    const float* iclr  = (const float*)d_in[4];
    const int*   wq    = (const int*)d_in[5];
    const float* wsc   = (const float*)d_in[6];
    float* out = (float*)d_out;

    static int attr_set = 0;
    if (!attr_set) {
        cudaFuncSetAttribute(mma_gemm_kernel,
                             cudaFuncAttributeMaxDynamicSharedMemorySize, GSM_TOTAL);
        cudaFuncSetAttribute(wkv7_scan_kernel,
                             cudaFuncAttributeMaxDynamicSharedMemorySize, SCAN_SMEM);
        attr_set = 1;
    }

    wkv7_prewin_kernel<<<Bdim * Hdim * (Tdim / 4) / 8, 256>>>(w, k, iclr);
    wconv_kernel<<<(Ddim * Ktot) / 1024, 256>>>(wq);
    wkv7_scan_kernel<<<Bdim * Hdim, 256, SCAN_SMEM>>>(r, k, v);

    dim3 grid(Ddim / 128, Mtot / 128);
    mma_gemm_kernel<<<grid, 256, GSM_TOTAL>>>(wsc, out);
}